// round 4
// baseline (speedup 1.0000x reference)
#include <cuda_runtime.h>
#include <cstdint>

#define BB 1024
#define SS 512
#define TT 64

// ---------------- device scratch ----------------
__device__ float4 g_E4[32 * 32];   // (E[i][j], E[i+32][j], E[i][j+32], E[i+32][j+32]) for i=row-pair ii, j=lane
__device__ double g_ll[BB];        // per-batch log-likelihood

// ---------------- f32x2 helpers ----------------
__device__ __forceinline__ unsigned long long pack2(float lo, float hi) {
    unsigned long long r;
    asm("mov.b64 %0, {%1, %2};" : "=l"(r) : "f"(lo), "f"(hi));
    return r;
}
__device__ __forceinline__ void unpack2(unsigned long long v, float& lo, float& hi) {
    asm("mov.b64 {%0, %1}, %2;" : "=f"(lo), "=f"(hi) : "l"(v));
}
__device__ __forceinline__ unsigned long long fma2(unsigned long long a, unsigned long long b, unsigned long long c) {
    unsigned long long r;
    asm("fma.rn.f32x2 %0, %1, %2, %3;" : "=l"(r) : "l"(a), "l"(b), "l"(c));
    return r;
}
__device__ __forceinline__ unsigned long long add2(unsigned long long a, unsigned long long b) {
    unsigned long long r;
    asm("add.rn.f32x2 %0, %1, %2;" : "=l"(r) : "l"(a), "l"(b));
    return r;
}
__device__ __forceinline__ float rcp_approx(float x) {
    float r;
    asm("rcp.approx.f32 %0, %1;" : "=f"(r) : "f"(x));
    return r;
}

// ---------------- prep ----------------
__global__ void crf_prep_kernel(const float* __restrict__ trans, float* __restrict__ d_out, int out_size) {
    int idx = blockIdx.x * blockDim.x + threadIdx.x;
    if (idx < 4096 && out_size >= 4097) d_out[1 + idx] = trans[idx];
    if (idx < 1024) {
        int ii = idx >> 5, l = idx & 31;
        float4 e;
        e.x = __expf(trans[ii * 64 + l]);
        e.y = __expf(trans[(ii + 32) * 64 + l]);
        e.z = __expf(trans[ii * 64 + l + 32]);
        e.w = __expf(trans[(ii + 32) * 64 + l + 32]);
        g_E4[idx] = e;
    }
}

// One linear-domain CRF step.
// Free vars: u0,u1,r_old,r_mid,C,unary,binary,t_prev,s_v,s_tm,w,lane,Ea,Eb,s_trans,FULL
// x0_,x1_ raw emissions for this step (from reg queue); par_ = step parity; s_ = step index.
#define CRF_STEP(x0_, x1_, s_, par_)                                             \
    do {                                                                         \
        float rho = r_old; r_old = r_mid;                                        \
        int tmv = s_tm[w][(s_)];                                                 \
        int t = tmv & 0xFFFF;                                                    \
        int mk = tmv >> 31;               /* 0 or -1 (all-ones) */               \
        float rcp_r = rcp_approx(rho);                                           \
        float lr = __logf(rho);                                                  \
        float ex0 = __expf(x0_);                                                 \
        float ex1 = __expf(x1_);                                                 \
        float g0 = ex0 * rcp_r;                                                  \
        float g1 = ex1 * rcp_r;                                                  \
        const int buf_ = (par_) & 1;                                             \
        __syncwarp();                                                            \
        const ulonglong2* vv = (const ulonglong2*)s_v[w][buf_];                  \
        unsigned long long A0 = 0ull, A1 = 0ull, B0 = 0ull, B1 = 0ull;           \
        _Pragma("unroll")                                                        \
        for (int ii = 0; ii < 16; ii++) {                                        \
            ulonglong2 vp = vv[ii];                                              \
            A0 = fma2(vp.x, Ea[2*ii],   A0);                                     \
            B0 = fma2(vp.x, Eb[2*ii],   B0);                                     \
            A1 = fma2(vp.y, Ea[2*ii+1], A1);                                     \
            B1 = fma2(vp.y, Eb[2*ii+1], B1);                                     \
        }                                                                        \
        unsigned long long As = add2(A0, A1);                                    \
        unsigned long long Bs = add2(B0, B1);                                    \
        float p_, q_, r_, u_;                                                    \
        unpack2(As, p_, q_);                                                     \
        unpack2(Bs, r_, u_);                                                     \
        float u0n = (p_ + q_) * g0;                                              \
        float u1n = (r_ + u_) * g1;                                              \
        u0 = mk ? u0 : u0n;                                                      \
        u1 = mk ? u1 : u1n;                                                      \
        s_v[w][buf_ ^ 1][lane] = pack2(u0, u1);                                  \
        float selx = (t < 32) ? (x0_) : (x1_);                                   \
        float uv = __shfl_sync(FULL, selx, t & 31);                              \
        float bv = s_trans[t_prev * 64 + t];                                     \
        unary  += mk ? 0.0f : uv;                                                \
        binary += mk ? 0.0f : bv;                                                \
        C      += mk ? 0.0  : (double)lr;                                        \
        t_prev = t;                                                              \
        r_mid = __shfl_sync(FULL, u0, 0);                                        \
    } while (0)

// ---------------- main: 1 warp per batch ----------------
__global__ __launch_bounds__(128) void crf_main_kernel(
    const float* __restrict__ inputs,
    const float* __restrict__ trans,
    const unsigned char* __restrict__ masks,
    const int* __restrict__ tags)
{
    __shared__ float s_trans[64 * 64];                 // 16 KB
    __shared__ unsigned long long s_v[4][2][32];       // double-buffered u exchange
    __shared__ int s_tm[4][SS];                        // tag | (mask<<31), per warp

    const int w    = threadIdx.x >> 5;
    const int lane = threadIdx.x & 31;
    const int b    = blockIdx.x * 4 + w;

    for (int i = threadIdx.x; i < 4096; i += 128) s_trans[i] = trans[i];
    // fuse tags+masks into SMEM (per-warp row)
    for (int s = lane; s < SS; s += 32) {
        int t = tags[b * SS + s];
        int m = masks[b * SS + s] ? (1 << 31) : 0;
        s_tm[w][s] = t | m;
    }
    __syncthreads();

    // E in registers: lane l owns output columns l and l+32
    unsigned long long Ea[32], Eb[32];
#pragma unroll
    for (int ii = 0; ii < 32; ii++) {
        float4 e = g_E4[ii * 32 + lane];
        Ea[ii] = pack2(e.x, e.y);
        Eb[ii] = pack2(e.z, e.w);
    }

    const float* xb = inputs + (size_t)b * SS * TT;
    const unsigned FULL = 0xFFFFFFFFu;

    // s = 0: alphas = x[0]; u = exp(alpha - c0), c0 = lane0 alpha
    float a00 = xb[lane];
    float a01 = xb[lane + 32];
    int tm0 = s_tm[w][0];
    int t_prev = tm0 & 0xFFFF;
    int mk0 = tm0 >> 31;
    float sel0 = (t_prev < 32) ? a00 : a01;
    float u0v = __shfl_sync(FULL, sel0, t_prev & 31);
    float unary  = mk0 ? 0.0f : u0v;
    float binary = 0.0f;

    float c0 = __shfl_sync(FULL, a00, 0);
    double C = (double)c0;
    float u0 = __expf(a00 - c0);
    float u1 = __expf(a01 - c0);
    s_v[w][1][lane] = pack2(u0, u1);     // step 1 reads buf = 1&1 = 1
    float r_old = 1.0f, r_mid = 1.0f;    // lane0 u = exp(0) = 1

    // depth-8 x prefetch queue (steps 1..8)
    float q0[8], q1[8];
#pragma unroll
    for (int u = 0; u < 8; u++) {
        q0[u] = xb[(1 + u) * TT + lane];
        q1[u] = xb[(1 + u) * TT + lane + 32];
    }

    int s = 1;
    for (int it = 0; it < 63; it++, s += 8) {      // steps 1..504
#pragma unroll
        for (int u = 0; u < 8; u++) {
            float x0 = q0[u], x1 = q1[u];
            int sp = s + u + 8;
            sp = (sp > SS - 1) ? (SS - 1) : sp;
            q0[u] = xb[sp * TT + lane];
            q1[u] = xb[sp * TT + lane + 32];
            CRF_STEP(x0, x1, s + u, s + u);
        }
    }
    // epilogue: steps 505..511 from queue slots 0..6
#pragma unroll
    for (int u = 0; u < 7; u++) {
        float x0 = q0[u], x1 = q1[u];
        CRF_STEP(x0, x1, s + u, s + u);
    }

    // log_norm = C + log(sum u)
    float sv = u0 + u1;
#pragma unroll
    for (int off = 16; off > 0; off >>= 1)
        sv += __shfl_xor_sync(FULL, sv, off);
    double log_norm = C + (double)__logf(sv);

    if (lane == 0)
        g_ll[b] = (double)unary + (double)binary - log_norm;
}

// ---------------- deterministic reduction ----------------
__global__ void crf_reduce_kernel(float* __restrict__ d_out) {
    __shared__ double sm[256];
    int t = threadIdx.x;
    double s = 0.0;
    for (int i = t; i < BB; i += 256) s += g_ll[i];
    sm[t] = s;
    __syncthreads();
    for (int off = 128; off > 0; off >>= 1) {
        if (t < off) sm[t] += sm[t + off];
        __syncthreads();
    }
    if (t == 0) d_out[0] = (float)(-sm[0] / (double)BB);
}

extern "C" void kernel_launch(void* const* d_in, const int* in_sizes, int n_in,
                              void* d_out, int out_size) {
    const float*         inputs = (const float*)d_in[0];
    const float*         trans  = (const float*)d_in[1];
    const unsigned char* masks  = (const unsigned char*)d_in[2];
    const int*           tags   = (const int*)d_in[3];
    float*               out    = (float*)d_out;

    crf_prep_kernel<<<8, 512>>>(trans, out, out_size);
    crf_main_kernel<<<256, 128>>>(inputs, trans, masks, tags);
    crf_reduce_kernel<<<1, 256>>>(out);
}

// round 5
// speedup vs baseline: 1.0837x; 1.0837x over previous
#include <cuda_runtime.h>
#include <cstdint>

#define BB 1024
#define SS 512
#define TT 64

// ---------------- device scratch ----------------
__device__ double g_ll[BB];        // per-batch log-likelihood

// ---------------- f32x2 helpers ----------------
__device__ __forceinline__ unsigned long long pack2(float lo, float hi) {
    unsigned long long r;
    asm("mov.b64 %0, {%1, %2};" : "=l"(r) : "f"(lo), "f"(hi));
    return r;
}
__device__ __forceinline__ void unpack2(unsigned long long v, float& lo, float& hi) {
    asm("mov.b64 {%0, %1}, %2;" : "=f"(lo), "=f"(hi) : "l"(v));
}
__device__ __forceinline__ unsigned long long fma2(unsigned long long a, unsigned long long b, unsigned long long c) {
    unsigned long long r;
    asm("fma.rn.f32x2 %0, %1, %2, %3;" : "=l"(r) : "l"(a), "l"(b), "l"(c));
    return r;
}
__device__ __forceinline__ unsigned long long add2(unsigned long long a, unsigned long long b) {
    unsigned long long r;
    asm("add.rn.f32x2 %0, %1, %2;" : "=l"(r) : "l"(a), "l"(b));
    return r;
}
__device__ __forceinline__ float rcp_approx(float x) {
    float r;
    asm("rcp.approx.f32 %0, %1;" : "=f"(r) : "f"(x));
    return r;
}

// One linear-domain CRF step.
// Free vars: u0,u1,r_old,r_mid,Cacc,path,t_prev,s_v,s_tm,w,lane,Ea,Eb,s_trans,FULL
#define CRF_STEP(x0_, x1_, s_, par_)                                             \
    do {                                                                         \
        float rho = r_old; r_old = r_mid;                                        \
        int tmv = s_tm[w][(s_)];                                                 \
        int t = tmv & 0xFFFF;                                                    \
        int mk = tmv >> 31;               /* 0 or -1 */                          \
        float rcp_r = rcp_approx(rho);                                           \
        float lr = __logf(rho);                                                  \
        float g0 = __expf(x0_) * rcp_r;                                          \
        float g1 = __expf(x1_) * rcp_r;                                          \
        const int buf_ = (par_) & 1;                                             \
        __syncwarp();                                                            \
        const ulonglong2* vv = (const ulonglong2*)s_v[w][buf_];                  \
        unsigned long long A0 = 0ull, A1 = 0ull, B0 = 0ull, B1 = 0ull;           \
        _Pragma("unroll")                                                        \
        for (int ii = 0; ii < 16; ii++) {                                        \
            ulonglong2 vp = vv[ii];                                              \
            A0 = fma2(vp.x, Ea[2*ii],   A0);                                     \
            B0 = fma2(vp.x, Eb[2*ii],   B0);                                     \
            A1 = fma2(vp.y, Ea[2*ii+1], A1);                                     \
            B1 = fma2(vp.y, Eb[2*ii+1], B1);                                     \
        }                                                                        \
        unsigned long long As = add2(A0, A1);                                    \
        unsigned long long Bs = add2(B0, B1);                                    \
        float p_, q_, r_, u_;                                                    \
        unpack2(As, p_, q_);                                                     \
        unpack2(Bs, r_, u_);                                                     \
        float u0n = (p_ + q_) * g0;                                              \
        float u1n = (r_ + u_) * g1;                                              \
        u0 = mk ? u0 : u0n;                                                      \
        u1 = mk ? u1 : u1n;                                                      \
        s_v[w][buf_ ^ 1][lane] = pack2(u0, u1);                                  \
        float selx = (t < 32) ? (x0_) : (x1_);                                   \
        float uv = __shfl_sync(FULL, selx, t & 31);                              \
        float bv = s_trans[t_prev * 64 + t];                                     \
        path += mk ? 0.0f : (uv + bv);                                           \
        Cacc += mk ? 0.0f : lr;                                                  \
        t_prev = t;                                                              \
        r_mid = __shfl_sync(FULL, u0, 0);                                        \
    } while (0)

// ---------------- main: 1 warp per batch (FIRST graph node -> ncu visibility) ----------------
__global__ __launch_bounds__(128) void crf_main_kernel(
    const float* __restrict__ inputs,
    const float* __restrict__ trans,
    const unsigned char* __restrict__ masks,
    const int* __restrict__ tags)
{
    __shared__ float s_trans[64 * 64];                 // 16 KB
    __shared__ unsigned long long s_v[4][2][32];       // double-buffered u exchange
    __shared__ int s_tm[4][SS];                        // tag | (mask<<31), per warp

    const int w    = threadIdx.x >> 5;
    const int lane = threadIdx.x & 31;
    const int b    = blockIdx.x * 4 + w;

    for (int i = threadIdx.x; i < 4096; i += 128) s_trans[i] = trans[i];
    for (int s = lane; s < SS; s += 32) {
        int t = tags[b * SS + s];
        int m = masks[b * SS + s] ? (1 << 31) : 0;
        s_tm[w][s] = t | m;
    }
    __syncthreads();

    // E in registers, computed per-block from s_trans (replaces prep kernel).
    // lane l owns output columns l and l+32:
    //   Ea[ii] = (E[ii][l],    E[ii+32][l]   )
    //   Eb[ii] = (E[ii][l+32], E[ii+32][l+32])
    unsigned long long Ea[32], Eb[32];
#pragma unroll
    for (int ii = 0; ii < 32; ii++) {
        Ea[ii] = pack2(__expf(s_trans[ii * 64 + lane]),
                       __expf(s_trans[(ii + 32) * 64 + lane]));
        Eb[ii] = pack2(__expf(s_trans[ii * 64 + lane + 32]),
                       __expf(s_trans[(ii + 32) * 64 + lane + 32]));
    }

    const float* xb = inputs + (size_t)b * SS * TT;
    const unsigned FULL = 0xFFFFFFFFu;

    // s = 0
    float a00 = xb[lane];
    float a01 = xb[lane + 32];
    int tm0 = s_tm[w][0];
    int t_prev = tm0 & 0xFFFF;
    int mk0 = tm0 >> 31;
    float sel0 = (t_prev < 32) ? a00 : a01;
    float u0v = __shfl_sync(FULL, sel0, t_prev & 31);
    float path = mk0 ? 0.0f : u0v;

    float c0 = __shfl_sync(FULL, a00, 0);
    float Cacc = 0.0f;                  // running log-scale beyond c0 (fp32)
    float u0 = __expf(a00 - c0);
    float u1 = __expf(a01 - c0);
    s_v[w][1][lane] = pack2(u0, u1);    // step 1 reads buf = 1
    float r_old = 1.0f, r_mid = 1.0f;   // lane0 u = exp(0) = 1

    // depth-8 x prefetch queue (steps 1..8)
    float q0[8], q1[8];
#pragma unroll
    for (int u = 0; u < 8; u++) {
        q0[u] = xb[(1 + u) * TT + lane];
        q1[u] = xb[(1 + u) * TT + lane + 32];
    }

    const float* xpf = xb + 9 * TT;     // prefetch pointer: step s+8 row
    int s = 1;
    for (int it = 0; it < 63; it++, s += 8) {      // steps 1..504
#pragma unroll
        for (int u = 0; u < 8; u++) {
            float x0 = q0[u], x1 = q1[u];
            // prefetch step s+u+8 (clamped to last row; one IMNMX)
            int sp = s + u + 8;
            sp = (sp > SS - 1) ? (SS - 1) : sp;
            const float* xr = xb + sp * TT;
            q0[u] = xr[lane];
            q1[u] = xr[lane + 32];
            CRF_STEP(x0, x1, s + u, s + u);
        }
    }
    (void)xpf;
    // epilogue: steps 505..511 from queue slots 0..6
#pragma unroll
    for (int u = 0; u < 7; u++) {
        float x0 = q0[u], x1 = q1[u];
        CRF_STEP(x0, x1, s + u, s + u);
    }

    // log_norm = c0 + Cacc + log(sum u)
    float sv = u0 + u1;
#pragma unroll
    for (int off = 16; off > 0; off >>= 1)
        sv += __shfl_xor_sync(FULL, sv, off);
    double log_norm = (double)c0 + (double)Cacc + (double)__logf(sv);

    if (lane == 0)
        g_ll[b] = (double)path - log_norm;
}

// ---------------- reduction + transitions copy ----------------
__global__ void crf_reduce_kernel(const float* __restrict__ trans,
                                  float* __restrict__ d_out, int out_size) {
    __shared__ double sm[256];
    int t = threadIdx.x;
    // copy transitions to out[1..4096]
    if (out_size >= 4097) {
        for (int i = t; i < 4096; i += 256) d_out[1 + i] = trans[i];
    }
    double s = 0.0;
    for (int i = t; i < BB; i += 256) s += g_ll[i];
    sm[t] = s;
    __syncthreads();
    for (int off = 128; off > 0; off >>= 1) {
        if (t < off) sm[t] += sm[t + off];
        __syncthreads();
    }
    if (t == 0) d_out[0] = (float)(-sm[0] / (double)BB);
}

extern "C" void kernel_launch(void* const* d_in, const int* in_sizes, int n_in,
                              void* d_out, int out_size) {
    const float*         inputs = (const float*)d_in[0];
    const float*         trans  = (const float*)d_in[1];
    const unsigned char* masks  = (const unsigned char*)d_in[2];
    const int*           tags   = (const int*)d_in[3];
    float*               out    = (float*)d_out;

    crf_main_kernel<<<256, 128>>>(inputs, trans, masks, tags);
    crf_reduce_kernel<<<1, 256>>>(trans, out, out_size);
}

// round 6
// speedup vs baseline: 1.1338x; 1.0463x over previous
#include <cuda_runtime.h>
#include <cstdint>

#define BB 1024
#define SS 512
#define TT 64

// ---------------- device scratch ----------------
__device__ double g_ll[BB];           // per-batch log-likelihood
__device__ unsigned int g_ctr = 0;    // last-block-done counter (reset each run by last block)

// ---------------- helpers ----------------
__device__ __forceinline__ unsigned long long pack2(float lo, float hi) {
    unsigned long long r;
    asm("mov.b64 %0, {%1, %2};" : "=l"(r) : "f"(lo), "f"(hi));
    return r;
}
__device__ __forceinline__ void unpack2(unsigned long long v, float& lo, float& hi) {
    asm("mov.b64 {%0, %1}, %2;" : "=f"(lo), "=f"(hi) : "l"(v));
}
__device__ __forceinline__ unsigned long long fma2(unsigned long long a, unsigned long long b, unsigned long long c) {
    unsigned long long r;
    asm("fma.rn.f32x2 %0, %1, %2, %3;" : "=l"(r) : "l"(a), "l"(b), "l"(c));
    return r;
}
__device__ __forceinline__ unsigned long long add2(unsigned long long a, unsigned long long b) {
    unsigned long long r;
    asm("add.rn.f32x2 %0, %1, %2;" : "=l"(r) : "l"(a), "l"(b));
    return r;
}
__device__ __forceinline__ float ex2_approx(float x) {
    float r; asm("ex2.approx.f32 %0, %1;" : "=f"(r) : "f"(x)); return r;
}
__device__ __forceinline__ float lg2_approx(float x) {
    float r; asm("lg2.approx.f32 %0, %1;" : "=f"(r) : "f"(x)); return r;
}

#define LOG2E 1.4426950408889634f
#define LN2   0.6931471805599453

// One linear-domain CRF step, log2-folded scaling.
// Free vars: u0,u1,r_old,r_mid,C2,path,t_prev,s_v,s_tm,w,lane,Ea,Eb,s_trans,FULL
#define CRF_STEP(x0_, x1_, s_, par_)                                             \
    do {                                                                         \
        float rho = r_old; r_old = r_mid;                                        \
        int tmv = s_tm[w][(s_)];                                                 \
        int t = tmv & 0xFFFF;                                                    \
        int mk = tmv >> 31;               /* 0 or -1 */                          \
        float l2r = lg2_approx(rho);                                             \
        float g0 = ex2_approx(fmaf((x0_), LOG2E, -l2r));                         \
        float g1 = ex2_approx(fmaf((x1_), LOG2E, -l2r));                         \
        const int buf_ = (par_) & 1;                                             \
        __syncwarp();                                                            \
        const ulonglong2* vv = (const ulonglong2*)s_v[w][buf_];                  \
        unsigned long long A0 = 0ull, A1 = 0ull, B0 = 0ull, B1 = 0ull;           \
        _Pragma("unroll")                                                        \
        for (int ii = 0; ii < 16; ii++) {                                        \
            ulonglong2 vp = vv[ii];                                              \
            A0 = fma2(vp.x, Ea[2*ii],   A0);                                     \
            B0 = fma2(vp.x, Eb[2*ii],   B0);                                     \
            A1 = fma2(vp.y, Ea[2*ii+1], A1);                                     \
            B1 = fma2(vp.y, Eb[2*ii+1], B1);                                     \
        }                                                                        \
        unsigned long long As = add2(A0, A1);                                    \
        unsigned long long Bs = add2(B0, B1);                                    \
        float p_, q_, r_, u_;                                                    \
        unpack2(As, p_, q_);                                                     \
        unpack2(Bs, r_, u_);                                                     \
        float u0n = (p_ + q_) * g0;                                              \
        float u1n = (r_ + u_) * g1;                                              \
        u0 = mk ? u0 : u0n;                                                      \
        u1 = mk ? u1 : u1n;                                                      \
        s_v[w][buf_ ^ 1][lane] = pack2(u0, u1);                                  \
        float selx = (t < 32) ? (x0_) : (x1_);                                   \
        float uv = __shfl_sync(FULL, selx, t & 31);                              \
        float bv = s_trans[t_prev * 64 + t];                                     \
        path += mk ? 0.0f : (uv + bv);                                           \
        C2   += mk ? 0.0f : l2r;                                                 \
        t_prev = t;                                                              \
        r_mid = __shfl_sync(FULL, u0, 0);                                        \
    } while (0)

// ---------------- fused main: recursion + transitions copy + last-block reduction ----------------
__global__ __launch_bounds__(128) void crf_main_kernel(
    const float* __restrict__ inputs,
    const float* __restrict__ trans,
    const unsigned char* __restrict__ masks,
    const int* __restrict__ tags,
    float* __restrict__ d_out, int out_size)
{
    __shared__ float s_trans[64 * 64];                 // 16 KB
    __shared__ unsigned long long s_v[4][2][32];       // double-buffered u exchange
    __shared__ int s_tm[4][SS];                        // tag | (mask<<31), per warp
    __shared__ bool s_last;
    __shared__ double s_red[128];

    const int w    = threadIdx.x >> 5;
    const int lane = threadIdx.x & 31;
    const int b    = blockIdx.x * 4 + w;

    // block 0 copies transitions to output (parallel with everything else)
    if (blockIdx.x == 0 && out_size >= 4097) {
        for (int i = threadIdx.x; i < 4096; i += 128) d_out[1 + i] = trans[i];
    }

    for (int i = threadIdx.x; i < 4096; i += 128) s_trans[i] = trans[i];
    for (int s = lane; s < SS; s += 32) {
        int t = tags[b * SS + s];
        int m = masks[b * SS + s] ? (1 << 31) : 0;
        s_tm[w][s] = t | m;
    }
    __syncthreads();

    // E in registers: lane l owns output columns l and l+32
    unsigned long long Ea[32], Eb[32];
#pragma unroll
    for (int ii = 0; ii < 32; ii++) {
        Ea[ii] = pack2(ex2_approx(s_trans[ii * 64 + lane] * LOG2E),
                       ex2_approx(s_trans[(ii + 32) * 64 + lane] * LOG2E));
        Eb[ii] = pack2(ex2_approx(s_trans[ii * 64 + lane + 32] * LOG2E),
                       ex2_approx(s_trans[(ii + 32) * 64 + lane + 32] * LOG2E));
    }

    const float* xb = inputs + (size_t)b * SS * TT;
    const unsigned FULL = 0xFFFFFFFFu;

    // s = 0
    float a00 = xb[lane];
    float a01 = xb[lane + 32];
    int tm0 = s_tm[w][0];
    int t_prev = tm0 & 0xFFFF;
    int mk0 = tm0 >> 31;
    float sel0 = (t_prev < 32) ? a00 : a01;
    float u0v = __shfl_sync(FULL, sel0, t_prev & 31);
    float path = mk0 ? 0.0f : u0v;

    float c0 = __shfl_sync(FULL, a00, 0);
    float C2 = 0.0f;                    // running log2-scale beyond c0
    float u0 = ex2_approx((a00 - c0) * LOG2E);
    float u1 = ex2_approx((a01 - c0) * LOG2E);
    s_v[w][1][lane] = pack2(u0, u1);    // step 1 reads buf = 1
    float r_old = 1.0f, r_mid = 1.0f;   // lane0 u = 1 exactly

    // depth-8 x prefetch queue (steps 1..8)
    float q0[8], q1[8];
#pragma unroll
    for (int u = 0; u < 8; u++) {
        q0[u] = xb[(1 + u) * TT + lane];
        q1[u] = xb[(1 + u) * TT + lane + 32];
    }

    int s = 1;
    for (int it = 0; it < 63; it++, s += 8) {      // steps 1..504
#pragma unroll
        for (int u = 0; u < 8; u++) {
            float x0 = q0[u], x1 = q1[u];
            int sp = s + u + 8;
            sp = (sp > SS - 1) ? (SS - 1) : sp;
            const float* xr = xb + sp * TT;
            q0[u] = xr[lane];
            q1[u] = xr[lane + 32];
            CRF_STEP(x0, x1, s + u, s + u);
        }
    }
    // epilogue: steps 505..511
#pragma unroll
    for (int u = 0; u < 7; u++) {
        float x0 = q0[u], x1 = q1[u];
        CRF_STEP(x0, x1, s + u, s + u);
    }

    // log_norm = c0 + ln2*C2 + log(sum u)
    float sv = u0 + u1;
#pragma unroll
    for (int off = 16; off > 0; off >>= 1)
        sv += __shfl_xor_sync(FULL, sv, off);
    double log_norm = (double)c0 + LN2 * (double)C2 + LN2 * (double)lg2_approx(sv);

    if (lane == 0)
        g_ll[b] = (double)path - log_norm;

    // ---- last-block reduction (deterministic fixed-order sum) ----
    __syncthreads();
    if (threadIdx.x == 0) {
        __threadfence();
        unsigned int old = atomicAdd(&g_ctr, 1u);
        s_last = (old == gridDim.x - 1);
    }
    __syncthreads();
    if (s_last) {
        int t = threadIdx.x;
        double acc = 0.0;
        for (int i = t; i < BB; i += 128) acc += g_ll[i];
        s_red[t] = acc;
        __syncthreads();
        for (int off = 64; off > 0; off >>= 1) {
            if (t < off) s_red[t] += s_red[t + off];
            __syncthreads();
        }
        if (t == 0) {
            d_out[0] = (float)(-s_red[0] / (double)BB);
            g_ctr = 0;   // reset for next graph replay
        }
    }
}

extern "C" void kernel_launch(void* const* d_in, const int* in_sizes, int n_in,
                              void* d_out, int out_size) {
    const float*         inputs = (const float*)d_in[0];
    const float*         trans  = (const float*)d_in[1];
    const unsigned char* masks  = (const unsigned char*)d_in[2];
    const int*           tags   = (const int*)d_in[3];
    float*               out    = (float*)d_out;

    crf_main_kernel<<<256, 128>>>(inputs, trans, masks, tags, out, out_size);
}

// round 7
// speedup vs baseline: 1.1856x; 1.0457x over previous
#include <cuda_runtime.h>
#include <cstdint>

#define BB 1024
#define SS 512
#define TT 64

// ---------------- device scratch ----------------
__device__ double g_ll[BB];
__device__ unsigned int g_ctr = 0;

// ---------------- helpers ----------------
__device__ __forceinline__ unsigned long long pack2(float lo, float hi) {
    unsigned long long r;
    asm("mov.b64 %0, {%1, %2};" : "=l"(r) : "f"(lo), "f"(hi));
    return r;
}
__device__ __forceinline__ void unpack2(unsigned long long v, float& lo, float& hi) {
    asm("mov.b64 {%0, %1}, %2;" : "=f"(lo), "=f"(hi) : "l"(v));
}
__device__ __forceinline__ unsigned long long fma2(unsigned long long a, unsigned long long b, unsigned long long c) {
    unsigned long long r;
    asm("fma.rn.f32x2 %0, %1, %2, %3;" : "=l"(r) : "l"(a), "l"(b), "l"(c));
    return r;
}
__device__ __forceinline__ float ex2_approx(float x) {
    float r; asm("ex2.approx.f32 %0, %1;" : "=f"(r) : "f"(x)); return r;
}
__device__ __forceinline__ float lg2_approx(float x) {
    float r; asm("lg2.approx.f32 %0, %1;" : "=f"(r) : "f"(x)); return r;
}
__device__ __forceinline__ float rcp_approx(float x) {
    float r; asm("rcp.approx.f32 %0, %1;" : "=f"(r) : "f"(x)); return r;
}

#define LOG2E 1.4426950408889634f
#define LN2   0.6931471805599453

// One linear-domain CRF step.
// ren_ = 1: apply renorm by stale rho (captured 2 steps earlier); cap_ = 1: capture rho.
// Free vars: u0,u1,r_pend,C2,path,t_prev,s_v,stm_p,w,lane,Ea,Eb,s_trans,FULL
#define CRF_STEP(x0_, x1_, par_, ren_, cap_)                                     \
    do {                                                                         \
        int tmv = *stm_p++;                                                      \
        int t = tmv & 0xFFFF;                                                    \
        int mk = tmv >> 31;               /* 0 or -1 */                          \
        float g0, g1, rinv = 1.0f;                                               \
        if (ren_) {                                                              \
            float l2r = lg2_approx(r_pend);                                      \
            rinv = rcp_approx(r_pend);                                           \
            g0 = ex2_approx(fmaf((x0_), LOG2E, -l2r));                           \
            g1 = ex2_approx(fmaf((x1_), LOG2E, -l2r));                           \
            C2 += l2r;                                                           \
        } else {                                                                 \
            g0 = ex2_approx((x0_) * LOG2E);                                      \
            g1 = ex2_approx((x1_) * LOG2E);                                      \
        }                                                                        \
        const int buf_ = (par_) & 1;                                             \
        asm volatile("" ::: "memory");                                           \
        const ulonglong2* vv = (const ulonglong2*)s_v[w][buf_];                  \
        unsigned long long A = 0ull, B = 0ull;                                   \
        _Pragma("unroll")                                                        \
        for (int ii = 0; ii < 16; ii++) {                                        \
            ulonglong2 vp = vv[ii];                                              \
            A = fma2(vp.x, Ea[2*ii],   A);                                       \
            B = fma2(vp.x, Eb[2*ii],   B);                                       \
            A = fma2(vp.y, Ea[2*ii+1], A);                                       \
            B = fma2(vp.y, Eb[2*ii+1], B);                                       \
        }                                                                        \
        float p_, q_, r_, u_;                                                    \
        unpack2(A, p_, q_);                                                      \
        unpack2(B, r_, u_);                                                      \
        float u0n = (p_ + q_) * g0;                                              \
        float u1n = (r_ + u_) * g1;                                              \
        if (ren_) {                                                              \
            u0 = mk ? u0 * rinv : u0n;                                           \
            u1 = mk ? u1 * rinv : u1n;                                           \
        } else {                                                                 \
            u0 = mk ? u0 : u0n;                                                  \
            u1 = mk ? u1 : u1n;                                                  \
        }                                                                        \
        asm volatile("" ::: "memory");                                           \
        s_v[w][buf_ ^ 1][lane] = pack2(u0, u1);                                  \
        float selx = (t < 32) ? (x0_) : (x1_);                                   \
        float uv = __shfl_sync(FULL, selx, t & 31);                              \
        float bv = s_trans[t_prev * 64 + t];                                     \
        path += mk ? 0.0f : (uv + bv);                                           \
        t_prev = t;                                                              \
        if (cap_) r_pend = __shfl_sync(FULL, u0, 0);                             \
    } while (0)

// ---------------- fused main ----------------
__global__ __launch_bounds__(128) void crf_main_kernel(
    const float* __restrict__ inputs,
    const float* __restrict__ trans,
    const unsigned char* __restrict__ masks,
    const int* __restrict__ tags,
    float* __restrict__ d_out, int out_size)
{
    __shared__ float s_trans[64 * 64];
    __shared__ unsigned long long s_v[4][2][32];
    __shared__ int s_tm[4][SS];
    __shared__ bool s_last;
    __shared__ double s_red[128];

    const int w    = threadIdx.x >> 5;
    const int lane = threadIdx.x & 31;
    const int b    = blockIdx.x * 4 + w;

    if (blockIdx.x == 0 && out_size >= 4097) {
        for (int i = threadIdx.x; i < 4096; i += 128) d_out[1 + i] = trans[i];
    }

    for (int i = threadIdx.x; i < 4096; i += 128) s_trans[i] = trans[i];
    for (int s = lane; s < SS; s += 32) {
        int t = tags[b * SS + s];
        int m = masks[b * SS + s] ? (1 << 31) : 0;
        s_tm[w][s] = t | m;
    }
    __syncthreads();

    // E in registers: lane l owns output columns l and l+32
    unsigned long long Ea[32], Eb[32];
#pragma unroll
    for (int ii = 0; ii < 32; ii++) {
        Ea[ii] = pack2(ex2_approx(s_trans[ii * 64 + lane] * LOG2E),
                       ex2_approx(s_trans[(ii + 32) * 64 + lane] * LOG2E));
        Eb[ii] = pack2(ex2_approx(s_trans[ii * 64 + lane + 32] * LOG2E),
                       ex2_approx(s_trans[(ii + 32) * 64 + lane + 32] * LOG2E));
    }

    const float* xb = inputs + (size_t)b * SS * TT;
    const unsigned FULL = 0xFFFFFFFFu;

    // s = 0
    float a00 = xb[lane];
    float a01 = xb[lane + 32];
    int tm0 = s_tm[w][0];
    int t_prev = tm0 & 0xFFFF;
    int mk0 = tm0 >> 31;
    float sel0 = (t_prev < 32) ? a00 : a01;
    float u0v = __shfl_sync(FULL, sel0, t_prev & 31);
    float path = mk0 ? 0.0f : u0v;

    float c0 = __shfl_sync(FULL, a00, 0);
    float C2 = 0.0f;
    float u0 = ex2_approx((a00 - c0) * LOG2E);
    float u1 = ex2_approx((a01 - c0) * LOG2E);
    s_v[w][1][lane] = pack2(u0, u1);    // step 1 reads buf 1
    float r_pend = 1.0f;                // lane0 u = 1 exactly

    // depth-8 x prefetch queue (steps 1..8)
    float q0[8], q1[8];
#pragma unroll
    for (int u = 0; u < 8; u++) {
        q0[u] = xb[(1 + u) * TT + lane];
        q1[u] = xb[(1 + u) * TT + lane + 32];
    }

    const int* stm_p = &s_tm[w][1];
    const float* xpf  = xb + 9 * TT;          // prefetch row for step s+8
    const float* xlim = xb + (SS - 1) * TT;   // clamp (last batch: stay in-bounds)

    int s = 1;
    for (int it = 0; it < 63; it++, s += 8) {      // steps 1..504
#pragma unroll
        for (int u = 0; u < 8; u++) {
            float x0 = q0[u], x1 = q1[u];
            const float* xr = (xpf < xlim) ? xpf : xlim;
            q0[u] = xr[lane];
            q1[u] = xr[lane + 32];
            xpf += TT;
            CRF_STEP(x0, x1, s + u,
                     (u == 0 || u == 4) ? 1 : 0,
                     (u == 2 || u == 6) ? 1 : 0);
        }
    }
    // epilogue: steps 505..511 (slots 0..6; phase preserved: (505-1)%8 == 0)
#pragma unroll
    for (int u = 0; u < 7; u++) {
        float x0 = q0[u], x1 = q1[u];
        CRF_STEP(x0, x1, s + u,
                 (u == 0 || u == 4) ? 1 : 0,
                 (u == 2) ? 1 : 0);
    }

    // log_norm = c0 + ln2*(C2 + lg2(sum u))
    float sv = u0 + u1;
#pragma unroll
    for (int off = 16; off > 0; off >>= 1)
        sv += __shfl_xor_sync(FULL, sv, off);
    double log_norm = (double)c0 + LN2 * ((double)C2 + (double)lg2_approx(sv));

    if (lane == 0)
        g_ll[b] = (double)path - log_norm;

    // ---- last-block reduction (deterministic fixed-order sum) ----
    __syncthreads();
    if (threadIdx.x == 0) {
        __threadfence();
        unsigned int old = atomicAdd(&g_ctr, 1u);
        s_last = (old == gridDim.x - 1);
    }
    __syncthreads();
    if (s_last) {
        int t = threadIdx.x;
        double acc = 0.0;
        for (int i = t; i < BB; i += 128) acc += g_ll[i];
        s_red[t] = acc;
        __syncthreads();
        for (int off = 64; off > 0; off >>= 1) {
            if (t < off) s_red[t] += s_red[t + off];
            __syncthreads();
        }
        if (t == 0) {
            d_out[0] = (float)(-s_red[0] / (double)BB);
            g_ctr = 0;
        }
    }
}

extern "C" void kernel_launch(void* const* d_in, const int* in_sizes, int n_in,
                              void* d_out, int out_size) {
    const float*         inputs = (const float*)d_in[0];
    const float*         trans  = (const float*)d_in[1];
    const unsigned char* masks  = (const unsigned char*)d_in[2];
    const int*           tags   = (const int*)d_in[3];
    float*               out    = (float*)d_out;

    crf_main_kernel<<<256, 128>>>(inputs, trans, masks, tags, out, out_size);
}

// round 8
// speedup vs baseline: 1.3130x; 1.1074x over previous
#include <cuda_runtime.h>
#include <cstdint>

#define BB 1024
#define SS 512
#define TT 64

// ---------------- device scratch ----------------
__device__ double g_ll[BB];
__device__ unsigned int g_ctr = 0;

// ---------------- helpers ----------------
__device__ __forceinline__ unsigned int hfma2_bf(unsigned int a, unsigned int b, unsigned int c) {
    unsigned int d;
    asm("fma.rn.bf16x2 %0, %1, %2, %3;" : "=r"(d) : "r"(a), "r"(b), "r"(c));
    return d;
}
__device__ __forceinline__ unsigned int hadd2_bf(unsigned int a, unsigned int b) {
    unsigned int d;
    asm("add.rn.bf16x2 %0, %1, %2;" : "=r"(d) : "r"(a), "r"(b));
    return d;
}
// pack two f32 into bf16x2: hi-half <- h_, lo-half <- l_
__device__ __forceinline__ unsigned int cvt_bf16x2(float h_, float l_) {
    unsigned int r;
    asm("cvt.rn.bf16x2.f32 %0, %1, %2;" : "=r"(r) : "f"(h_), "f"(l_));
    return r;
}
__device__ __forceinline__ float bf_lo(unsigned int h) { return __uint_as_float(h << 16); }
__device__ __forceinline__ float bf_hi(unsigned int h) { return __uint_as_float(h & 0xFFFF0000u); }
__device__ __forceinline__ float ex2_approx(float x) {
    float r; asm("ex2.approx.f32 %0, %1;" : "=f"(r) : "f"(x)); return r;
}
__device__ __forceinline__ float lg2_approx(float x) {
    float r; asm("lg2.approx.f32 %0, %1;" : "=f"(r) : "f"(x)); return r;
}
__device__ __forceinline__ float rcp_approx(float x) {
    float r; asm("rcp.approx.f32 %0, %1;" : "=f"(r) : "f"(x)); return r;
}

#define LOG2E 1.4426950408889634f
#define LN2   0.6931471805599453

// One linear-domain CRF step; bf16x2 matvec, fp32 state.
// Free vars: u0,u1,r_pend,C2,s_v4,smkp,w,lane,E0,E1,FULL
#define CRF_STEP(xq_, par_, ren_, cap_)                                          \
    do {                                                                         \
        int mk = *smkp++;                                                        \
        float g0, g1, rinv = 1.0f;                                               \
        if (ren_) {                                                              \
            float l2r = lg2_approx(r_pend);                                      \
            rinv = rcp_approx(r_pend);                                           \
            g0 = ex2_approx(fmaf((xq_).x, LOG2E, -l2r));                         \
            g1 = ex2_approx(fmaf((xq_).y, LOG2E, -l2r));                         \
            C2 += l2r;                                                           \
        } else {                                                                 \
            g0 = ex2_approx((xq_).x * LOG2E);                                    \
            g1 = ex2_approx((xq_).y * LOG2E);                                    \
        }                                                                        \
        const int buf_ = (par_) & 1;                                             \
        asm volatile("" ::: "memory");                                           \
        const uint4* vv = (const uint4*)&s_v4[w][buf_][0];                       \
        unsigned int a00 = 0u, a01 = 0u, a10 = 0u, a11 = 0u;                     \
        _Pragma("unroll")                                                        \
        for (int c = 0; c < 8; c++) {                                            \
            uint4 vp = vv[c];                                                    \
            a00 = hfma2_bf(vp.x, E0[4*c],   a00);                                \
            a10 = hfma2_bf(vp.x, E1[4*c],   a10);                                \
            a01 = hfma2_bf(vp.y, E0[4*c+1], a01);                                \
            a11 = hfma2_bf(vp.y, E1[4*c+1], a11);                                \
            a00 = hfma2_bf(vp.z, E0[4*c+2], a00);                                \
            a10 = hfma2_bf(vp.z, E1[4*c+2], a10);                                \
            a01 = hfma2_bf(vp.w, E0[4*c+3], a01);                                \
            a11 = hfma2_bf(vp.w, E1[4*c+3], a11);                                \
        }                                                                        \
        unsigned int h0 = hadd2_bf(a00, a01);                                    \
        unsigned int h1 = hadd2_bf(a10, a11);                                    \
        float w0 = bf_lo(h0) + bf_hi(h0);                                        \
        float w1 = bf_lo(h1) + bf_hi(h1);                                        \
        float u0n = w0 * g0;                                                     \
        float u1n = w1 * g1;                                                     \
        float u0r = (ren_) ? u0 * rinv : u0;                                     \
        float u1r = (ren_) ? u1 * rinv : u1;                                     \
        u0 = mk ? u0r : u0n;                                                     \
        u1 = mk ? u1r : u1n;                                                     \
        asm volatile("" ::: "memory");                                           \
        ((unsigned int*)&s_v4[w][buf_ ^ 1][0])[lane] = cvt_bf16x2(u1, u0);       \
        if (cap_) r_pend = __shfl_sync(FULL, u0, 0);                             \
    } while (0)

// ---------------- fused main ----------------
__global__ __launch_bounds__(128) void crf_main_kernel(
    const float* __restrict__ inputs,
    const float* __restrict__ trans,
    const unsigned char* __restrict__ masks,
    const int* __restrict__ tags,
    float* __restrict__ d_out, int out_size)
{
    __shared__ float s_trans[64 * 64];            // 16 KB
    __shared__ uint4 s_v4[4][2][8];               // per-warp double-buffered bf16x2 u exchange
    __shared__ unsigned char s_mk[4][SS];         // per-step masks
    __shared__ bool s_last;
    __shared__ double s_red[128];

    const int w    = threadIdx.x >> 5;
    const int lane = threadIdx.x & 31;
    const int b    = blockIdx.x * 4 + w;

    if (blockIdx.x == 0 && out_size >= 4097) {
        for (int i = threadIdx.x; i < 4096; i += 128) d_out[1 + i] = trans[i];
    }

    for (int i = threadIdx.x; i < 4096; i += 128) s_trans[i] = trans[i];
    for (int s = lane; s < SS; s += 32) s_mk[w][s] = masks[b * SS + s];
    __syncthreads();

    // E in bf16x2 registers. lane l owns OUTPUT columns j0=2l, j1=2l+1.
    // E0[ii] = (lo: E[2ii][j0], hi: E[2ii+1][j0]), E1[ii] likewise for j1.
    unsigned int E0[32], E1[32];
    {
        const int j0 = 2 * lane, j1 = 2 * lane + 1;
#pragma unroll
        for (int ii = 0; ii < 32; ii++) {
            float e0l = ex2_approx(s_trans[(2 * ii) * 64 + j0] * LOG2E);
            float e0h = ex2_approx(s_trans[(2 * ii + 1) * 64 + j0] * LOG2E);
            float e1l = ex2_approx(s_trans[(2 * ii) * 64 + j1] * LOG2E);
            float e1h = ex2_approx(s_trans[(2 * ii + 1) * 64 + j1] * LOG2E);
            E0[ii] = cvt_bf16x2(e0h, e0l);
            E1[ii] = cvt_bf16x2(e1h, e1l);
        }
    }

    const float* xb = inputs + (size_t)b * SS * TT;
    const unsigned FULL = 0xFFFFFFFFu;

    // ---- path score precompute (independent of the recursion) ----
    float pathAcc = 0.0f;
    for (int s0 = lane; s0 < SS; s0 += 32) {
        int t = tags[b * SS + s0];
        unsigned char m = masks[b * SS + s0];
        float xv = __ldg(&xb[s0 * TT + t]);
        float term = m ? 0.0f : xv;
        if (s0 > 0) {
            int tp = tags[b * SS + s0 - 1];
            term += m ? 0.0f : s_trans[tp * 64 + t];
        }
        pathAcc += term;
    }
#pragma unroll
    for (int off = 16; off > 0; off >>= 1)
        pathAcc += __shfl_xor_sync(FULL, pathAcc, off);

    // ---- s = 0 init ----
    float2 x0q = *(const float2*)(xb + 2 * lane);     // (x[2l], x[2l+1])
    float c0 = __shfl_sync(FULL, x0q.x, 0);           // alpha ref = x[b][0][0]
    float C2 = 0.0f;
    float u0 = ex2_approx((x0q.x - c0) * LOG2E);
    float u1 = ex2_approx((x0q.y - c0) * LOG2E);
    ((unsigned int*)&s_v4[w][1][0])[lane] = cvt_bf16x2(u1, u0);   // step 1 reads buf 1
    float r_pend = 1.0f;                              // lane0 u[0] = 1 exactly

    // depth-8 x prefetch queue (steps 1..8), float2 per lane
    float2 q[8];
#pragma unroll
    for (int u = 0; u < 8; u++)
        q[u] = *(const float2*)(xb + (1 + u) * TT + 2 * lane);

    const unsigned char* smkp = &s_mk[w][1];
    const float* xpf  = xb + 9 * TT;
    const float* xlim = xb + (SS - 1) * TT;

    int s = 1;
    for (int it = 0; it < 63; it++, s += 8) {      // steps 1..504
#pragma unroll
        for (int u = 0; u < 8; u++) {
            float2 xq = q[u];
            const float* xr = (xpf < xlim) ? xpf : xlim;
            q[u] = *(const float2*)(xr + 2 * lane);
            xpf += TT;
            CRF_STEP(xq, s + u,
                     (u == 0 || u == 4) ? 1 : 0,
                     (u == 2 || u == 6) ? 1 : 0);
        }
    }
    // epilogue: steps 505..511 (phase preserved)
#pragma unroll
    for (int u = 0; u < 7; u++) {
        float2 xq = q[u];
        CRF_STEP(xq, s + u,
                 (u == 0 || u == 4) ? 1 : 0,
                 (u == 2) ? 1 : 0);
    }

    // log_norm = c0 + ln2*(C2 + lg2(sum u))
    float sv = u0 + u1;
#pragma unroll
    for (int off = 16; off > 0; off >>= 1)
        sv += __shfl_xor_sync(FULL, sv, off);
    double log_norm = (double)c0 + LN2 * ((double)C2 + (double)lg2_approx(sv));

    if (lane == 0)
        g_ll[b] = (double)pathAcc - log_norm;

    // ---- last-block deterministic reduction ----
    __syncthreads();
    if (threadIdx.x == 0) {
        __threadfence();
        unsigned int old = atomicAdd(&g_ctr, 1u);
        s_last = (old == gridDim.x - 1);
    }
    __syncthreads();
    if (s_last) {
        int t = threadIdx.x;
        double acc = 0.0;
        for (int i = t; i < BB; i += 128) acc += g_ll[i];
        s_red[t] = acc;
        __syncthreads();
        for (int off = 64; off > 0; off >>= 1) {
            if (t < off) s_red[t] += s_red[t + off];
            __syncthreads();
        }
        if (t == 0) {
            d_out[0] = (float)(-s_red[0] / (double)BB);
            g_ctr = 0;
        }
    }
}

extern "C" void kernel_launch(void* const* d_in, const int* in_sizes, int n_in,
                              void* d_out, int out_size) {
    const float*         inputs = (const float*)d_in[0];
    const float*         trans  = (const float*)d_in[1];
    const unsigned char* masks  = (const unsigned char*)d_in[2];
    const int*           tags   = (const int*)d_in[3];
    float*               out    = (float*)d_out;

    crf_main_kernel<<<256, 128>>>(inputs, trans, masks, tags, out, out_size);
}